// round 14
// baseline (speedup 1.0000x reference)
#include <cuda_runtime.h>
#include <math.h>

#define Nn 16384
#define Bg 16
#define Hd 64
#define H2 128
#define Kn 16
#define DPAD 1280
#define NS (Bg*DPAD)        // 20480 padded slots
#define MAXT 1600
#define NSLOT 40            // DPAD/32
#define BN_EPS 1e-5f

// packed f32x2 helpers (bit-exact pairs of IEEE fp32 FMAs)
#define FMA2(acc, a, b) asm("fma.rn.f32x2 %0, %1, %2, %0;" : "+l"(acc) : "l"(a), "l"(b))
#define PACKF2(dst, x)  asm("mov.b64 %0, {%1, %1};" : "=l"(dst) : "r"(__float_as_uint(x)))
#define UNPACKF2(lo, hi, src) asm("mov.b64 {%0, %1}, %2;" : "=r"(lo), "=r"(hi) : "l"(src))

// ---------------- scratch ----------------
__device__ float d_h[Nn*Hd];
__device__ float d_e[Nn*Hd];
__device__ float d_hT[Hd*NS];       // slot-compacted, per-graph aligned regions
__device__ float d_u[Nn*H2];
__device__ float d_v[Nn*H2];
__device__ float d_sqs[NS];         // per-slot squared norms
__device__ float d_g[Bg*Hd];
__device__ float d_dist[(size_t)NS*DPAD];
__device__ int   d_idx[Nn*Kn];
__device__ int   d_partner[Nn];
__device__ int   d_validA[Nn];
__device__ int   d_validB[Nn];
__device__ int   d_gstart[Bg+1];
__device__ int   d_glist[Nn];
__device__ int   d_gcount[Bg];

// ---------------- graph bounds ----------------
__global__ void k_bounds(const int* __restrict__ batch){
    int b = threadIdx.x;
    if (b > Bg) return;
    if (b == Bg){ d_gstart[Bg] = Nn; return; }
    int lo = 0, hi = Nn;
    while (lo < hi){ int mid = (lo + hi) >> 1; if (batch[mid] < b) lo = mid + 1; else hi = mid; }
    d_gstart[b] = lo;
}

// ---------------- input net + init (fused) ----------------
__global__ void k_input(const float* __restrict__ x, const float* __restrict__ dn,
                        const float* __restrict__ w, const float* __restrict__ b){
    int tid = blockIdx.x*256 + threadIdx.x;
    int i = tid >> 6, c = tid & 63;
    float acc = __ldg(&b[c]);
    #pragma unroll
    for (int d = 0; d < 4; d++) acc += x[i*4+d] * __ldg(&dn[d]) * __ldg(&w[c*4+d]);
    d_h[i*Hd+c] = fmaxf(acc, 0.f);
    if (c == 0){ d_validA[i] = 1; d_glist[i] = i; }
    if (tid < NS) d_sqs[tid] = 0.f;
    if (tid < Bg) d_gcount[tid] = d_gstart[tid+1] - d_gstart[tid];
}

// ---------------- transpose (gather via glist into slot space) + fused sq ----------------
__global__ void k_transpose(int layer){
    const float* h = layer ? d_e : d_h;
    __shared__ float tile[32][33];
    int n0 = blockIdx.x*32, d0 = blockIdx.y*32;
    int g = n0 / DPAD, sl0 = n0 - g*DPAD;
    int p0 = d_gstart[g];
    int cnt = d_gcount[g]; if (cnt > DPAD) cnt = DPAD;
    int tx = threadIdx.x, ty = threadIdx.y;       // (32,8)
    #pragma unroll
    for (int r = ty; r < 32; r += 8){
        int sl = sl0 + r;
        int node = d_glist[p0 + ((sl < cnt) ? sl : 0)];
        tile[r][tx] = h[node*Hd + d0 + tx];
    }
    __syncthreads();
    #pragma unroll
    for (int r = ty; r < 32; r += 8) d_hT[(d0+r)*NS + n0 + tx] = tile[tx][r];
    if (ty == 0){
        float ssum = 0.f;
        #pragma unroll 8
        for (int k = 0; k < 32; k++){ float v = tile[tx][k]; ssum = fmaf(v, v, ssum); }
        atomicAdd(&d_sqs[n0+tx], ssum);
    }
}

// ---------------- kNN distances: 16 queries x 4 candidates/thread, f32x2 ----------------
__global__ void __launch_bounds__(256) k_dist(int layer){
    const float* h = layer ? d_e : d_h;
    __shared__ __align__(16) float hq[Hd*16];     // [d][16]
    __shared__ float sqq[16];
    __shared__ int   sh_g, sh_qs0;

    int tid = threadIdx.x;
    if (tid == 0){
        int bt = blockIdx.x, acc = 0, gg = -1, qq0 = 0;
        for (int g2 = 0; g2 < Bg; g2++){
            int cg = d_gcount[g2]; if (cg > DPAD) cg = DPAD;
            int tiles = (cg + 15) >> 4;
            if (bt < acc + tiles){ gg = g2; qq0 = (bt - acc)*16; break; }
            acc += tiles;
        }
        sh_g = gg; sh_qs0 = qq0;
    }
    __syncthreads();
    if (sh_g < 0) return;
    int g = sh_g, qs0 = sh_qs0;
    int p0    = d_gstart[g];
    int gbase = g * DPAD;
    int cnt   = d_gcount[g]; if (cnt > DPAD) cnt = DPAD;
    int nq    = cnt - qs0; if (nq > 16) nq = 16;

    {   // stage query features [d][16]
        int q = tid >> 4, d4 = (tid & 15) << 2;
        int qq = (q < nq) ? q : (nq - 1);
        int qi = d_glist[p0 + qs0 + qq];
        float4 v = *(const float4*)&h[qi*Hd + d4];
        hq[(d4+0)*16+q] = v.x; hq[(d4+1)*16+q] = v.y;
        hq[(d4+2)*16+q] = v.z; hq[(d4+3)*16+q] = v.w;
        if (d4 == 0) sqq[q] = d_sqs[gbase + qs0 + qq];
    }
    __syncthreads();
    int s0 = gbase + qs0;                          // dist row base (slot space)

    for (int c0 = 0; c0 < cnt; c0 += 1024){
        int ca  = c0 + tid*4;
        int caS = (ca < cnt) ? ca : 0;
        float4 sqc = *(const float4*)&d_sqs[gbase + caS];

        unsigned long long acc2[4][8];
        #pragma unroll
        for (int c = 0; c < 4; c++)
            #pragma unroll
            for (int q = 0; q < 8; q++) acc2[c][q] = 0ULL;

        const float4* pc = (const float4*)&d_hT[gbase + caS];  // +NS/4 per d
        const ulonglong2* hr = (const ulonglong2*)hq;
        #pragma unroll 2
        for (int d = 0; d < Hd; d++){
            float4 cv = *pc; pc += NS/4;
            unsigned long long c0d, c1d, c2d, c3d;
            PACKF2(c0d, cv.x); PACKF2(c1d, cv.y); PACKF2(c2d, cv.z); PACKF2(c3d, cv.w);
            ulonglong2 qA = hr[0], qB = hr[1], qC = hr[2], qD = hr[3];
            hr += 4;
            FMA2(acc2[0][0], qA.x, c0d); FMA2(acc2[0][1], qA.y, c0d);
            FMA2(acc2[0][2], qB.x, c0d); FMA2(acc2[0][3], qB.y, c0d);
            FMA2(acc2[0][4], qC.x, c0d); FMA2(acc2[0][5], qC.y, c0d);
            FMA2(acc2[0][6], qD.x, c0d); FMA2(acc2[0][7], qD.y, c0d);
            FMA2(acc2[1][0], qA.x, c1d); FMA2(acc2[1][1], qA.y, c1d);
            FMA2(acc2[1][2], qB.x, c1d); FMA2(acc2[1][3], qB.y, c1d);
            FMA2(acc2[1][4], qC.x, c1d); FMA2(acc2[1][5], qC.y, c1d);
            FMA2(acc2[1][6], qD.x, c1d); FMA2(acc2[1][7], qD.y, c1d);
            FMA2(acc2[2][0], qA.x, c2d); FMA2(acc2[2][1], qA.y, c2d);
            FMA2(acc2[2][2], qB.x, c2d); FMA2(acc2[2][3], qB.y, c2d);
            FMA2(acc2[2][4], qC.x, c2d); FMA2(acc2[2][5], qC.y, c2d);
            FMA2(acc2[2][6], qD.x, c2d); FMA2(acc2[2][7], qD.y, c2d);
            FMA2(acc2[3][0], qA.x, c3d); FMA2(acc2[3][1], qA.y, c3d);
            FMA2(acc2[3][2], qB.x, c3d); FMA2(acc2[3][3], qB.y, c3d);
            FMA2(acc2[3][4], qC.x, c3d); FMA2(acc2[3][5], qC.y, c3d);
            FMA2(acc2[3][6], qD.x, c3d); FMA2(acc2[3][7], qD.y, c3d);
        }
        if (ca < cnt){
            #pragma unroll
            for (int qp = 0; qp < 8; qp++){
                unsigned int e0,o0,e1,o1,e2,o2,e3,o3;
                UNPACKF2(e0,o0,acc2[0][qp]); UNPACKF2(e1,o1,acc2[1][qp]);
                UNPACKF2(e2,o2,acc2[2][qp]); UNPACKF2(e3,o3,acc2[3][qp]);
                float se = sqq[2*qp], so = sqq[2*qp+1];
                float4 ve = make_float4(se+sqc.x-2.f*__uint_as_float(e0),
                                        se+sqc.y-2.f*__uint_as_float(e1),
                                        se+sqc.z-2.f*__uint_as_float(e2),
                                        se+sqc.w-2.f*__uint_as_float(e3));
                float4 vo = make_float4(so+sqc.x-2.f*__uint_as_float(o0),
                                        so+sqc.y-2.f*__uint_as_float(o1),
                                        so+sqc.z-2.f*__uint_as_float(o2),
                                        so+sqc.w-2.f*__uint_as_float(o3));
                *(float4*)&d_dist[(size_t)(s0+2*qp  )*DPAD + ca] = ve;
                *(float4*)&d_dist[(size_t)(s0+2*qp+1)*DPAD + ca] = vo;
            }
        }
    }
}

// ---------------- kNN selection: warp per slot, float4 register cache ----------------
__global__ void __launch_bounds__(256) k_sel(int layer){
    int warp = threadIdx.x >> 5, lane = threadIdx.x & 31;
    int s = blockIdx.x*8 + warp;                  // slot
    int g = s / DPAD, sl = s - g*DPAD;
    int p0  = d_gstart[g];
    int cnt = d_gcount[g]; if (cnt > DPAD) cnt = DPAD;
    if (sl >= cnt) return;

    int qi = d_glist[p0 + sl];
    const float* row = d_dist + (size_t)s*DPAD;

    // lane owns candidates c = 128*k4 + 4*lane + ci ; ascending k <=> ascending c per lane
    float v[NSLOT];
    #pragma unroll
    for (int k4 = 0; k4 < 10; k4++){
        int c = 128*k4 + 4*lane;
        float4 f = (c < cnt) ? *(const float4*)&row[c]
                             : make_float4(INFINITY,INFINITY,INFINITY,INFINITY);
        if (c     >= cnt) f.x = INFINITY;
        if (c + 1 >= cnt) f.y = INFINITY;
        if (c + 2 >= cnt) f.z = INFINITY;
        if (c + 3 >= cnt) f.w = INFINITY;
        v[k4*4+0] = f.x; v[k4*4+1] = f.y; v[k4*4+2] = f.z; v[k4*4+3] = f.w;
    }

    for (int r = 0; r < Kn; r++){
        float bd = INFINITY; int bc = 0x7fffffff;
        #pragma unroll
        for (int k = 0; k < NSLOT; k++){
            int c = 128*(k >> 2) + 4*lane + (k & 3);
            if (v[k] < bd){ bd = v[k]; bc = c; }
        }
        #pragma unroll
        for (int off = 16; off > 0; off >>= 1){
            float od = __shfl_down_sync(0xffffffffu, bd, off);
            int   oc = __shfl_down_sync(0xffffffffu, bc, off);
            if (od < bd || (od == bd && oc < bc)){ bd = od; bc = oc; }
        }
        int win = __shfl_sync(0xffffffffu, bc, 0);
        if (lane == 0) d_idx[qi*Kn + r] = d_glist[p0 + win];
        if (((win >> 2) & 31) == lane){
            int ks = ((win >> 7) << 2) | (win & 3);
            #pragma unroll
            for (int k = 0; k < NSLOT; k++) if (k == ks) v[k] = INFINITY;
        }
    }
}

// ---------------- edgeconv stage 1: scalar, 4 nodes per weight read ----------------
#define UVN 16
__global__ void __launch_bounds__(128) k_uv(int layer, const float* __restrict__ l0w,
                     const float* __restrict__ l0b,
                     const float* __restrict__ g0, const float* __restrict__ b0){
    const int t = threadIdx.x;
    const int* valid = layer ? d_validB : d_validA;
    const float* h   = layer ? d_e      : d_h;
    __shared__ float Wsh[H2*129];
    __shared__ float hsh[4][Hd];
    for (int p = t; p < H2*H2; p += H2){
        int o = p >> 7, c = p & 127;
        Wsh[o*129 + c] = __ldg(&l0w[p]);
    }
    float s  = __ldg(&g0[t]) / sqrtf(1.0f + BN_EPS);
    float bb = __ldg(&l0b[t])*s + __ldg(&b0[t]);
    __syncthreads();

    int base = blockIdx.x * UVN;
    for (int r4 = 0; r4 < UVN; r4 += 4){
        #pragma unroll
        for (int p = t; p < 4*Hd; p += 128){
            int n = p >> 6, c = p & 63;
            int i = base + r4 + n;
            hsh[n][c] = valid[i] ? h[i*Hd+c] : 0.f;
        }
        __syncthreads();
        const float* wr = &Wsh[t*129];
        float su0=0,su1=0,su2=0,su3=0, sv0=0,sv1=0,sv2=0,sv3=0;
        #pragma unroll 4
        for (int c = 0; c < Hd; c++){
            float a  = wr[c];
            float bw = wr[Hd+c];
            float amb = a - bw;
            float h0 = hsh[0][c], h1 = hsh[1][c], h2 = hsh[2][c], h3 = hsh[3][c];
            su0 = fmaf(h0, amb, su0); sv0 = fmaf(h0, bw, sv0);
            su1 = fmaf(h1, amb, su1); sv1 = fmaf(h1, bw, sv1);
            su2 = fmaf(h2, amb, su2); sv2 = fmaf(h2, bw, sv2);
            su3 = fmaf(h3, amb, su3); sv3 = fmaf(h3, bw, sv3);
        }
        int i0 = base + r4;
        if (valid[i0  ]){ d_u[(i0  )*H2+t] = su0*s + bb; d_v[(i0  )*H2+t] = sv0*s; }
        if (valid[i0+1]){ d_u[(i0+1)*H2+t] = su1*s + bb; d_v[(i0+1)*H2+t] = sv1*s; }
        if (valid[i0+2]){ d_u[(i0+2)*H2+t] = su2*s + bb; d_v[(i0+2)*H2+t] = sv2*s; }
        if (valid[i0+3]){ d_u[(i0+3)*H2+t] = su3*s + bb; d_v[(i0+3)*H2+t] = sv3*s; }
        __syncthreads();
    }
}

// ---------------- edgeconv stage 2: f32x2 mainloop ----------------
#define EN 16
__global__ void __launch_bounds__(256) k_edge(int layer, const float* __restrict__ l1w,
                       const float* __restrict__ l1b,
                       const float* __restrict__ g1, const float* __restrict__ b1){
    const int tid = threadIdx.x;
    const int grp = tid >> 6, t = tid & 63, lane = tid & 31;
    const int* valid = layer ? d_validB : d_validA;
    float*     out   = layer ? d_h      : d_e;

    __shared__ float W1t[H2*65];
    __shared__ __align__(16) float rsh[4][H2*16];

    for (int p = tid; p < Hd*H2; p += 256){
        int o = p >> 7, r = p & 127;
        W1t[r*65+o] = __ldg(&l1w[p]);
    }
    float s  = __ldg(&g1[t]) / sqrtf(1.0f + BN_EPS);
    float bb = __ldg(&l1b[t])*s + __ldg(&b1[t]);
    __syncthreads();

    int base = blockIdx.x * EN;
    for (int round = 0; round < 4; round++){
        int i = base + round*4 + grp;
        if (!valid[i]) continue;

        float u0 = d_u[i*H2+t], u1 = d_u[i*H2+64+t];
        int myj = (lane < Kn) ? d_idx[i*Kn+lane] : 0;
        float r0[16], r1[16];
        #pragma unroll
        for (int e = 0; e < 16; e++){
            int j = __shfl_sync(0xffffffffu, myj, e);
            r0[e] = fmaxf(u0 + __ldg(&d_v[j*H2+t]),    0.f);
            r1[e] = fmaxf(u1 + __ldg(&d_v[j*H2+64+t]), 0.f);
        }
        float* R = rsh[grp];
        #pragma unroll
        for (int q = 0; q < 4; q++){
            *(float4*)&R[t*16+q*4]      = make_float4(r0[q*4],r0[q*4+1],r0[q*4+2],r0[q*4+3]);
            *(float4*)&R[(t+64)*16+q*4] = make_float4(r1[q*4],r1[q*4+1],r1[q*4+2],r1[q*4+3]);
        }
        asm volatile("bar.sync %0, 64;" :: "r"(grp+1) : "memory");

        unsigned long long acc2[8];
        #pragma unroll
        for (int q = 0; q < 8; q++) acc2[q] = 0ULL;
        const ulonglong2* Rr = (const ulonglong2*)R;
        #pragma unroll 2
        for (int r = 0; r < H2; r++){
            ulonglong2 pA = Rr[0], pB = Rr[1], pC = Rr[2], pD = Rr[3];
            Rr += 4;
            float w = W1t[r*65+t];
            unsigned long long w2; PACKF2(w2, w);
            FMA2(acc2[0], pA.x, w2); FMA2(acc2[1], pA.y, w2);
            FMA2(acc2[2], pB.x, w2); FMA2(acc2[3], pB.y, w2);
            FMA2(acc2[4], pC.x, w2); FMA2(acc2[5], pC.y, w2);
            FMA2(acc2[6], pD.x, w2); FMA2(acc2[7], pD.y, w2);
        }
        float o = 0.f;
        #pragma unroll
        for (int q = 0; q < 8; q++){
            unsigned int lo, hi; UNPACKF2(lo, hi, acc2[q]);
            o += fmaxf(__uint_as_float(lo)*s + bb, 0.f);
            o += fmaxf(__uint_as_float(hi)*s + bb, 0.f);
        }
        out[i*Hd+t] = o;
        asm volatile("bar.sync %0, 64;" :: "r"(grp+1) : "memory");
    }
}

// ---------------- cluster pool: mutual max-distance matching ----------------
__global__ void k_partner(int layer){
    const float* h     = layer ? d_h : d_e;
    const int*   valid = layer ? d_validB : d_validA;
    int lane = threadIdx.x & 31, wid = threadIdx.x >> 5;
    int i = blockIdx.x*4 + wid;
    if (!valid[i]){ if (lane == 0) d_partner[i] = i; return; }

    int n = lane & 15, hf = lane >> 4;
    int j = d_idx[i*Kn+n];
    const float4* pj = (const float4*)&h[j*Hd + hf*32];
    const float4* pi = (const float4*)&h[i*Hd + hf*32];
    float ssum = 0.f;
    #pragma unroll
    for (int q = 0; q < 8; q++){
        float4 a = __ldg(&pj[q]);
        float4 b = pi[q];
        float dx = a.x-b.x, dy = a.y-b.y, dz = a.z-b.z, dw = a.w-b.w;
        ssum += dx*dx + dy*dy + dz*dz + dw*dw;
    }
    ssum += __shfl_xor_sync(0xffffffffu, ssum, 16);
    float w = (j == i) ? -INFINITY : sqrtf(ssum + 1e-12f);
    int bk = n;
    #pragma unroll
    for (int off = 8; off > 0; off >>= 1){
        float ow = __shfl_down_sync(0xffffffffu, w,  off);
        int   ok = __shfl_down_sync(0xffffffffu, bk, off);
        int   oj = __shfl_down_sync(0xffffffffu, j,  off);
        if (ow > w || (ow == w && ok < bk)){ w = ow; bk = ok; j = oj; }
    }
    if (lane == 0) d_partner[i] = valid[j] ? j : i;
}

// ---------------- pool (parallel; zeroes slot-sq for next layer) ----------------
__global__ void k_pool(int layer){
    int tid = blockIdx.x*256 + threadIdx.x;
    int i = tid >> 6, t = tid & 63;
    float* h   = layer ? d_h : d_e;
    const int* vin  = layer ? d_validB : d_validA;
    int*       vout = layer ? d_validA : d_validB;
    if (tid < NS) d_sqs[tid] = 0.f;
    if (!vin[i]){ if (t == 0) vout[i] = 0; return; }
    int p = d_partner[i];
    int keep = 1;
    if (p != i && d_partner[p] == i){
        if (p < i) keep = 0;
        else h[i*Hd+t] = fmaxf(h[i*Hd+t], h[p*Hd+t]);
    }
    if (t == 0) vout[i] = keep;
}

// ---------------- order-preserving compaction ----------------
__global__ void k_compact(){
    int g = blockIdx.x, t = threadIdx.x;
    int lane = t & 31, warp = t >> 5;
    int s = d_gstart[g], e2 = d_gstart[g+1];
    __shared__ int wsum[8], woff[8], base;
    if (t == 0) base = 0;
    __syncthreads();
    for (int st = s; st < e2; st += 256){
        int node = st + t;
        int f = (node < e2) ? d_validB[node] : 0;
        unsigned m = __ballot_sync(0xffffffffu, f);
        int wpre = __popc(m & ((1u << lane) - 1u));
        if (lane == 0) wsum[warp] = __popc(m);
        __syncthreads();
        if (t == 0){
            int r = base;
            for (int w2 = 0; w2 < 8; w2++){ woff[w2] = r; r += wsum[w2]; }
            base = r;
        }
        __syncthreads();
        if (f) d_glist[s + woff[warp] + wpre] = node;
        __syncthreads();
    }
    if (t == 0) d_gcount[g] = base;
}

// ---------------- global max-pool ----------------
__global__ void k_globalpool(){
    int b = blockIdx.x, t = threadIdx.x;
    int c = t & 63, rg = t >> 6;
    int s = d_gstart[b], e2 = d_gstart[b+1];
    float m = -1e30f;
    for (int i = s + rg; i < e2; i += 8)
        if (d_validA[i]) m = fmaxf(m, d_h[i*Hd+c]);
    __shared__ float red[512];
    red[t] = m; __syncthreads();
    if (t < 256) red[t] = fmaxf(red[t], red[t+256]);
    __syncthreads();
    if (t < 128) red[t] = fmaxf(red[t], red[t+128]);
    __syncthreads();
    if (t < 64) d_g[b*Hd + c] = fmaxf(red[t], red[t+64]);
}

// ---------------- output MLP ----------------
__global__ void k_mlp(const float* __restrict__ o0w, const float* __restrict__ o0b,
                      const float* __restrict__ o1w, const float* __restrict__ o1b,
                      const float* __restrict__ o2w, const float* __restrict__ o2b,
                      float* __restrict__ out){
    int t = threadIdx.x;
    int b = t >> 6, c = t & 63;
    __shared__ float g1s[Bg*Hd], g2s[Bg*Hd];
    float acc = __ldg(&o0b[c]);
    for (int d = 0; d < Hd; d++) acc += d_g[b*Hd+d] * __ldg(&o0w[c*Hd+d]);
    g1s[t] = fmaxf(acc, 0.f);
    __syncthreads();
    acc = __ldg(&o1b[c]);
    for (int d = 0; d < Hd; d++) acc += g1s[b*Hd+d] * __ldg(&o1w[c*Hd+d]);
    g2s[t] = fmaxf(acc, 0.f);
    __syncthreads();
    if (t < Bg){
        float a = __ldg(&o2b[0]);
        for (int d = 0; d < Hd; d++) a += g2s[t*Hd+d] * __ldg(&o2w[d]);
        out[t] = a;
    }
}

// ---------------- launch ----------------
extern "C" void kernel_launch(void* const* d_in, const int* in_sizes, int n_in,
                              void* d_out, int out_size){
    const float* x     = (const float*)d_in[0];
    const int*   batch = (const int*)  d_in[1];
    const float* dn    = (const float*)d_in[2];
    const float* inw   = (const float*)d_in[3];
    const float* inb   = (const float*)d_in[4];
    const float* A[2][8];
    for (int l = 0; l < 2; l++)
        for (int q = 0; q < 8; q++)
            A[l][q] = (const float*)d_in[5 + l*8 + q];
    const float* o0w = (const float*)d_in[21];
    const float* o0b = (const float*)d_in[22];
    const float* o1w = (const float*)d_in[23];
    const float* o1b = (const float*)d_in[24];
    const float* o2w = (const float*)d_in[25];
    const float* o2b = (const float*)d_in[26];
    float* out = (float*)d_out;

    k_bounds<<<1, 32>>>(batch);                 // 0
    k_input<<<Nn/4, 256>>>(x, dn, inw, inb);    // 1

    dim3 tgrid(NS/32, Hd/32), tthr(32, 8);
    for (int l = 0; l < 2; l++){
        k_transpose<<<tgrid, tthr>>>(l);        // 2
        k_dist<<<MAXT, 256>>>(l);               // 3 <- profiled slot
        k_sel<<<NS/8, 256>>>(l);
        k_uv<<<(Nn + UVN - 1)/UVN, H2>>>(l, A[l][0], A[l][1], A[l][2], A[l][3]);
        k_edge<<<(Nn + EN - 1)/EN, 256>>>(l, A[l][4], A[l][5], A[l][6], A[l][7]);
        k_partner<<<Nn/4, 128>>>(l);
        k_pool<<<Nn/4, 256>>>(l);
        if (l == 0) k_compact<<<Bg, 256>>>();
    }

    k_globalpool<<<Bg, 512>>>();
    k_mlp<<<1, Bg*Hd>>>(o0w, o0b, o1w, o1b, o2w, o2b, out);
}

// round 15
// speedup vs baseline: 1.0726x; 1.0726x over previous
#include <cuda_runtime.h>
#include <math.h>

#define Nn 16384
#define Bg 16
#define Hd 64
#define H2 128
#define Kn 16
#define DPAD 1280
#define NS (Bg*DPAD)        // 20480 padded slots
#define MAXT 1600
#define NSLOT 40            // DPAD/32
#define BN_EPS 1e-5f

// packed f32x2 helpers (bit-exact pairs of IEEE fp32 FMAs)
#define FMA2(acc, a, b) asm("fma.rn.f32x2 %0, %1, %2, %0;" : "+l"(acc) : "l"(a), "l"(b))
#define PACKF2(dst, x)  asm("mov.b64 %0, {%1, %1};" : "=l"(dst) : "r"(__float_as_uint(x)))
#define UNPACKF2(lo, hi, src) asm("mov.b64 {%0, %1}, %2;" : "=r"(lo), "=r"(hi) : "l"(src))

// ---------------- scratch ----------------
__device__ float d_h[Nn*Hd];
__device__ float d_e[Nn*Hd];
__device__ float d_hT[Hd*NS];       // slot-compacted, per-graph aligned regions
__device__ float d_u[Nn*H2];
__device__ float d_v[Nn*H2];
__device__ float d_sqs[NS];         // per-slot squared norms
__device__ float d_g[Bg*Hd];
__device__ float d_dist[(size_t)NS*DPAD];
__device__ int   d_idx[Nn*Kn];
__device__ int   d_partner[Nn];
__device__ int   d_validA[Nn];
__device__ int   d_validB[Nn];
__device__ int   d_gstart[Bg+1];
__device__ int   d_glist[Nn];
__device__ int   d_gcount[Bg];

// ---------------- graph bounds ----------------
__global__ void k_bounds(const int* __restrict__ batch){
    int b = threadIdx.x;
    if (b > Bg) return;
    if (b == Bg){ d_gstart[Bg] = Nn; return; }
    int lo = 0, hi = Nn;
    while (lo < hi){ int mid = (lo + hi) >> 1; if (batch[mid] < b) lo = mid + 1; else hi = mid; }
    d_gstart[b] = lo;
}

// ---------------- input net + init (fused) ----------------
__global__ void k_input(const float* __restrict__ x, const float* __restrict__ dn,
                        const float* __restrict__ w, const float* __restrict__ b){
    int tid = blockIdx.x*256 + threadIdx.x;
    int i = tid >> 6, c = tid & 63;
    float acc = __ldg(&b[c]);
    #pragma unroll
    for (int d = 0; d < 4; d++) acc += x[i*4+d] * __ldg(&dn[d]) * __ldg(&w[c*4+d]);
    d_h[i*Hd+c] = fmaxf(acc, 0.f);
    if (c == 0){ d_validA[i] = 1; d_glist[i] = i; }
    if (tid < NS) d_sqs[tid] = 0.f;
    if (tid < Bg) d_gcount[tid] = d_gstart[tid+1] - d_gstart[tid];
}

// ---------------- transpose (gather via glist into slot space) + fused sq ----------------
__global__ void k_transpose(int layer){
    const float* h = layer ? d_e : d_h;
    __shared__ float tile[32][33];
    int n0 = blockIdx.x*32, d0 = blockIdx.y*32;
    int g = n0 / DPAD, sl0 = n0 - g*DPAD;
    int p0 = d_gstart[g];
    int cnt = d_gcount[g]; if (cnt > DPAD) cnt = DPAD;
    int tx = threadIdx.x, ty = threadIdx.y;       // (32,8)
    #pragma unroll
    for (int r = ty; r < 32; r += 8){
        int sl = sl0 + r;
        int node = d_glist[p0 + ((sl < cnt) ? sl : 0)];
        tile[r][tx] = h[node*Hd + d0 + tx];
    }
    __syncthreads();
    #pragma unroll
    for (int r = ty; r < 32; r += 8) d_hT[(d0+r)*NS + n0 + tx] = tile[tx][r];
    if (ty == 0){
        float ssum = 0.f;
        #pragma unroll 8
        for (int k = 0; k < 32; k++){ float v = tile[tx][k]; ssum = fmaf(v, v, ssum); }
        atomicAdd(&d_sqs[n0+tx], ssum);
    }
}

// ---------------- kNN distances: 16 queries x 2 candidates/thread, f32x2 ----------------
__global__ void __launch_bounds__(256) k_dist(int layer){
    const float* h = layer ? d_e : d_h;
    __shared__ __align__(16) float hq[Hd*16];     // [d][16]
    __shared__ float sqq[16];
    __shared__ int   sh_g, sh_qs0;

    int tid = threadIdx.x;
    if (tid == 0){
        int bt = blockIdx.x, acc = 0, gg = -1, qq0 = 0;
        for (int g2 = 0; g2 < Bg; g2++){
            int cg = d_gcount[g2]; if (cg > DPAD) cg = DPAD;
            int tiles = (cg + 15) >> 4;
            if (bt < acc + tiles){ gg = g2; qq0 = (bt - acc)*16; break; }
            acc += tiles;
        }
        sh_g = gg; sh_qs0 = qq0;
    }
    __syncthreads();
    if (sh_g < 0) return;
    int g = sh_g, qs0 = sh_qs0;
    int p0    = d_gstart[g];
    int gbase = g * DPAD;
    int cnt   = d_gcount[g]; if (cnt > DPAD) cnt = DPAD;
    int nq    = cnt - qs0; if (nq > 16) nq = 16;

    {   // stage query features [d][16]
        int q = tid >> 4, d4 = (tid & 15) << 2;
        int qq = (q < nq) ? q : (nq - 1);
        int qi = d_glist[p0 + qs0 + qq];
        float4 v = *(const float4*)&h[qi*Hd + d4];
        hq[(d4+0)*16+q] = v.x; hq[(d4+1)*16+q] = v.y;
        hq[(d4+2)*16+q] = v.z; hq[(d4+3)*16+q] = v.w;
        if (d4 == 0) sqq[q] = d_sqs[gbase + qs0 + qq];
    }
    __syncthreads();
    int s0 = gbase + qs0;                          // dist row base (slot space)

    for (int c0 = 0; c0 < cnt; c0 += 512){
        int ca  = c0 + tid*2;                      // even -> float2-aligned
        int caS = (ca < cnt) ? ca : 0;
        float2 sqc = *(const float2*)&d_sqs[gbase + caS];

        unsigned long long A2[8], B2[8];           // cand0 / cand1 x 16 query-halves
        #pragma unroll
        for (int q = 0; q < 8; q++){ A2[q] = 0ULL; B2[q] = 0ULL; }

        const float2* pc = (const float2*)&d_hT[gbase + caS];  // +NS/2 per d
        const ulonglong2* hr = (const ulonglong2*)hq;
        #pragma unroll 4
        for (int d = 0; d < Hd; d++){
            float2 cv = *pc; pc += NS/2;
            unsigned long long ca2, cb2;
            PACKF2(ca2, cv.x); PACKF2(cb2, cv.y);
            ulonglong2 qA = hr[0], qB = hr[1], qC = hr[2], qD = hr[3];
            hr += 4;
            FMA2(A2[0], qA.x, ca2); FMA2(A2[1], qA.y, ca2);
            FMA2(A2[2], qB.x, ca2); FMA2(A2[3], qB.y, ca2);
            FMA2(A2[4], qC.x, ca2); FMA2(A2[5], qC.y, ca2);
            FMA2(A2[6], qD.x, ca2); FMA2(A2[7], qD.y, ca2);
            FMA2(B2[0], qA.x, cb2); FMA2(B2[1], qA.y, cb2);
            FMA2(B2[2], qB.x, cb2); FMA2(B2[3], qB.y, cb2);
            FMA2(B2[4], qC.x, cb2); FMA2(B2[5], qC.y, cb2);
            FMA2(B2[6], qD.x, cb2); FMA2(B2[7], qD.y, cb2);
        }
        if (ca + 1 < cnt){
            #pragma unroll
            for (int qp = 0; qp < 8; qp++){
                unsigned int a_lo, a_hi, b_lo, b_hi;
                UNPACKF2(a_lo, a_hi, A2[qp]); UNPACKF2(b_lo, b_hi, B2[qp]);
                float se = sqq[2*qp], so = sqq[2*qp+1];
                *(float2*)&d_dist[(size_t)(s0+2*qp  )*DPAD + ca] =
                    make_float2(se + sqc.x - 2.f*__uint_as_float(a_lo),
                                se + sqc.y - 2.f*__uint_as_float(b_lo));
                *(float2*)&d_dist[(size_t)(s0+2*qp+1)*DPAD + ca] =
                    make_float2(so + sqc.x - 2.f*__uint_as_float(a_hi),
                                so + sqc.y - 2.f*__uint_as_float(b_hi));
            }
        } else if (ca < cnt){                      // odd tail: store single candidate
            #pragma unroll
            for (int qp = 0; qp < 8; qp++){
                unsigned int a_lo, a_hi; UNPACKF2(a_lo, a_hi, A2[qp]);
                d_dist[(size_t)(s0+2*qp  )*DPAD + ca] = sqq[2*qp]   + sqc.x - 2.f*__uint_as_float(a_lo);
                d_dist[(size_t)(s0+2*qp+1)*DPAD + ca] = sqq[2*qp+1] + sqc.x - 2.f*__uint_as_float(a_hi);
            }
        }
    }
}

// ---------------- kNN selection: warp per slot, float4 register cache ----------------
__global__ void __launch_bounds__(256) k_sel(int layer){
    int warp = threadIdx.x >> 5, lane = threadIdx.x & 31;
    int s = blockIdx.x*8 + warp;                  // slot
    int g = s / DPAD, sl = s - g*DPAD;
    int p0  = d_gstart[g];
    int cnt = d_gcount[g]; if (cnt > DPAD) cnt = DPAD;
    if (sl >= cnt) return;

    int qi = d_glist[p0 + sl];
    const float* row = d_dist + (size_t)s*DPAD;

    // lane owns candidates c = 128*k4 + 4*lane + ci ; ascending k <=> ascending c per lane
    float v[NSLOT];
    #pragma unroll
    for (int k4 = 0; k4 < 10; k4++){
        int c = 128*k4 + 4*lane;
        float4 f = (c < cnt) ? *(const float4*)&row[c]
                             : make_float4(INFINITY,INFINITY,INFINITY,INFINITY);
        if (c     >= cnt) f.x = INFINITY;
        if (c + 1 >= cnt) f.y = INFINITY;
        if (c + 2 >= cnt) f.z = INFINITY;
        if (c + 3 >= cnt) f.w = INFINITY;
        v[k4*4+0] = f.x; v[k4*4+1] = f.y; v[k4*4+2] = f.z; v[k4*4+3] = f.w;
    }

    for (int r = 0; r < Kn; r++){
        float bd = INFINITY; int bc = 0x7fffffff;
        #pragma unroll
        for (int k = 0; k < NSLOT; k++){
            int c = 128*(k >> 2) + 4*lane + (k & 3);
            if (v[k] < bd){ bd = v[k]; bc = c; }
        }
        #pragma unroll
        for (int off = 16; off > 0; off >>= 1){
            float od = __shfl_down_sync(0xffffffffu, bd, off);
            int   oc = __shfl_down_sync(0xffffffffu, bc, off);
            if (od < bd || (od == bd && oc < bc)){ bd = od; bc = oc; }
        }
        int win = __shfl_sync(0xffffffffu, bc, 0);
        if (lane == 0) d_idx[qi*Kn + r] = d_glist[p0 + win];
        if (((win >> 2) & 31) == lane){
            int ks = ((win >> 7) << 2) | (win & 3);
            #pragma unroll
            for (int k = 0; k < NSLOT; k++) if (k == ks) v[k] = INFINITY;
        }
    }
}

// ---------------- edgeconv stage 1: scalar, 4 nodes per weight read ----------------
#define UVN 16
__global__ void __launch_bounds__(128) k_uv(int layer, const float* __restrict__ l0w,
                     const float* __restrict__ l0b,
                     const float* __restrict__ g0, const float* __restrict__ b0){
    const int t = threadIdx.x;
    const int* valid = layer ? d_validB : d_validA;
    const float* h   = layer ? d_e      : d_h;
    __shared__ float Wsh[H2*129];
    __shared__ float hsh[4][Hd];
    for (int p = t; p < H2*H2; p += H2){
        int o = p >> 7, c = p & 127;
        Wsh[o*129 + c] = __ldg(&l0w[p]);
    }
    float s  = __ldg(&g0[t]) / sqrtf(1.0f + BN_EPS);
    float bb = __ldg(&l0b[t])*s + __ldg(&b0[t]);
    __syncthreads();

    int base = blockIdx.x * UVN;
    for (int r4 = 0; r4 < UVN; r4 += 4){
        #pragma unroll
        for (int p = t; p < 4*Hd; p += 128){
            int n = p >> 6, c = p & 63;
            int i = base + r4 + n;
            hsh[n][c] = valid[i] ? h[i*Hd+c] : 0.f;
        }
        __syncthreads();
        const float* wr = &Wsh[t*129];
        float su0=0,su1=0,su2=0,su3=0, sv0=0,sv1=0,sv2=0,sv3=0;
        #pragma unroll 4
        for (int c = 0; c < Hd; c++){
            float a  = wr[c];
            float bw = wr[Hd+c];
            float amb = a - bw;
            float h0 = hsh[0][c], h1 = hsh[1][c], h2 = hsh[2][c], h3 = hsh[3][c];
            su0 = fmaf(h0, amb, su0); sv0 = fmaf(h0, bw, sv0);
            su1 = fmaf(h1, amb, su1); sv1 = fmaf(h1, bw, sv1);
            su2 = fmaf(h2, amb, su2); sv2 = fmaf(h2, bw, sv2);
            su3 = fmaf(h3, amb, su3); sv3 = fmaf(h3, bw, sv3);
        }
        int i0 = base + r4;
        if (valid[i0  ]){ d_u[(i0  )*H2+t] = su0*s + bb; d_v[(i0  )*H2+t] = sv0*s; }
        if (valid[i0+1]){ d_u[(i0+1)*H2+t] = su1*s + bb; d_v[(i0+1)*H2+t] = sv1*s; }
        if (valid[i0+2]){ d_u[(i0+2)*H2+t] = su2*s + bb; d_v[(i0+2)*H2+t] = sv2*s; }
        if (valid[i0+3]){ d_u[(i0+3)*H2+t] = su3*s + bb; d_v[(i0+3)*H2+t] = sv3*s; }
        __syncthreads();
    }
}

// ---------------- edgeconv stage 2: f32x2 mainloop ----------------
#define EN 16
__global__ void __launch_bounds__(256) k_edge(int layer, const float* __restrict__ l1w,
                       const float* __restrict__ l1b,
                       const float* __restrict__ g1, const float* __restrict__ b1){
    const int tid = threadIdx.x;
    const int grp = tid >> 6, t = tid & 63, lane = tid & 31;
    const int* valid = layer ? d_validB : d_validA;
    float*     out   = layer ? d_h      : d_e;

    __shared__ float W1t[H2*65];
    __shared__ __align__(16) float rsh[4][H2*16];

    for (int p = tid; p < Hd*H2; p += 256){
        int o = p >> 7, r = p & 127;
        W1t[r*65+o] = __ldg(&l1w[p]);
    }
    float s  = __ldg(&g1[t]) / sqrtf(1.0f + BN_EPS);
    float bb = __ldg(&l1b[t])*s + __ldg(&b1[t]);
    __syncthreads();

    int base = blockIdx.x * EN;
    for (int round = 0; round < 4; round++){
        int i = base + round*4 + grp;
        if (!valid[i]) continue;

        float u0 = d_u[i*H2+t], u1 = d_u[i*H2+64+t];
        int myj = (lane < Kn) ? d_idx[i*Kn+lane] : 0;
        float r0[16], r1[16];
        #pragma unroll
        for (int e = 0; e < 16; e++){
            int j = __shfl_sync(0xffffffffu, myj, e);
            r0[e] = fmaxf(u0 + __ldg(&d_v[j*H2+t]),    0.f);
            r1[e] = fmaxf(u1 + __ldg(&d_v[j*H2+64+t]), 0.f);
        }
        float* R = rsh[grp];
        #pragma unroll
        for (int q = 0; q < 4; q++){
            *(float4*)&R[t*16+q*4]      = make_float4(r0[q*4],r0[q*4+1],r0[q*4+2],r0[q*4+3]);
            *(float4*)&R[(t+64)*16+q*4] = make_float4(r1[q*4],r1[q*4+1],r1[q*4+2],r1[q*4+3]);
        }
        asm volatile("bar.sync %0, 64;" :: "r"(grp+1) : "memory");

        unsigned long long acc2[8];
        #pragma unroll
        for (int q = 0; q < 8; q++) acc2[q] = 0ULL;
        const ulonglong2* Rr = (const ulonglong2*)R;
        #pragma unroll 2
        for (int r = 0; r < H2; r++){
            ulonglong2 pA = Rr[0], pB = Rr[1], pC = Rr[2], pD = Rr[3];
            Rr += 4;
            float w = W1t[r*65+t];
            unsigned long long w2; PACKF2(w2, w);
            FMA2(acc2[0], pA.x, w2); FMA2(acc2[1], pA.y, w2);
            FMA2(acc2[2], pB.x, w2); FMA2(acc2[3], pB.y, w2);
            FMA2(acc2[4], pC.x, w2); FMA2(acc2[5], pC.y, w2);
            FMA2(acc2[6], pD.x, w2); FMA2(acc2[7], pD.y, w2);
        }
        float o = 0.f;
        #pragma unroll
        for (int q = 0; q < 8; q++){
            unsigned int lo, hi; UNPACKF2(lo, hi, acc2[q]);
            o += fmaxf(__uint_as_float(lo)*s + bb, 0.f);
            o += fmaxf(__uint_as_float(hi)*s + bb, 0.f);
        }
        out[i*Hd+t] = o;
        asm volatile("bar.sync %0, 64;" :: "r"(grp+1) : "memory");
    }
}

// ---------------- cluster pool: mutual max-distance matching ----------------
__global__ void k_partner(int layer){
    const float* h     = layer ? d_h : d_e;
    const int*   valid = layer ? d_validB : d_validA;
    int lane = threadIdx.x & 31, wid = threadIdx.x >> 5;
    int i = blockIdx.x*4 + wid;
    if (!valid[i]){ if (lane == 0) d_partner[i] = i; return; }

    int n = lane & 15, hf = lane >> 4;
    int j = d_idx[i*Kn+n];
    const float4* pj = (const float4*)&h[j*Hd + hf*32];
    const float4* pi = (const float4*)&h[i*Hd + hf*32];
    float ssum = 0.f;
    #pragma unroll
    for (int q = 0; q < 8; q++){
        float4 a = __ldg(&pj[q]);
        float4 b = pi[q];
        float dx = a.x-b.x, dy = a.y-b.y, dz = a.z-b.z, dw = a.w-b.w;
        ssum += dx*dx + dy*dy + dz*dz + dw*dw;
    }
    ssum += __shfl_xor_sync(0xffffffffu, ssum, 16);
    float w = (j == i) ? -INFINITY : sqrtf(ssum + 1e-12f);
    int bk = n;
    #pragma unroll
    for (int off = 8; off > 0; off >>= 1){
        float ow = __shfl_down_sync(0xffffffffu, w,  off);
        int   ok = __shfl_down_sync(0xffffffffu, bk, off);
        int   oj = __shfl_down_sync(0xffffffffu, j,  off);
        if (ow > w || (ow == w && ok < bk)){ w = ow; bk = ok; j = oj; }
    }
    if (lane == 0) d_partner[i] = valid[j] ? j : i;
}

// ---------------- pool (parallel; zeroes slot-sq for next layer) ----------------
__global__ void k_pool(int layer){
    int tid = blockIdx.x*256 + threadIdx.x;
    int i = tid >> 6, t = tid & 63;
    float* h   = layer ? d_h : d_e;
    const int* vin  = layer ? d_validB : d_validA;
    int*       vout = layer ? d_validA : d_validB;
    if (tid < NS) d_sqs[tid] = 0.f;
    if (!vin[i]){ if (t == 0) vout[i] = 0; return; }
    int p = d_partner[i];
    int keep = 1;
    if (p != i && d_partner[p] == i){
        if (p < i) keep = 0;
        else h[i*Hd+t] = fmaxf(h[i*Hd+t], h[p*Hd+t]);
    }
    if (t == 0) vout[i] = keep;
}

// ---------------- order-preserving compaction ----------------
__global__ void k_compact(){
    int g = blockIdx.x, t = threadIdx.x;
    int lane = t & 31, warp = t >> 5;
    int s = d_gstart[g], e2 = d_gstart[g+1];
    __shared__ int wsum[8], woff[8], base;
    if (t == 0) base = 0;
    __syncthreads();
    for (int st = s; st < e2; st += 256){
        int node = st + t;
        int f = (node < e2) ? d_validB[node] : 0;
        unsigned m = __ballot_sync(0xffffffffu, f);
        int wpre = __popc(m & ((1u << lane) - 1u));
        if (lane == 0) wsum[warp] = __popc(m);
        __syncthreads();
        if (t == 0){
            int r = base;
            for (int w2 = 0; w2 < 8; w2++){ woff[w2] = r; r += wsum[w2]; }
            base = r;
        }
        __syncthreads();
        if (f) d_glist[s + woff[warp] + wpre] = node;
        __syncthreads();
    }
    if (t == 0) d_gcount[g] = base;
}

// ---------------- global max-pool ----------------
__global__ void k_globalpool(){
    int b = blockIdx.x, t = threadIdx.x;
    int c = t & 63, rg = t >> 6;
    int s = d_gstart[b], e2 = d_gstart[b+1];
    float m = -1e30f;
    for (int i = s + rg; i < e2; i += 8)
        if (d_validA[i]) m = fmaxf(m, d_h[i*Hd+c]);
    __shared__ float red[512];
    red[t] = m; __syncthreads();
    if (t < 256) red[t] = fmaxf(red[t], red[t+256]);
    __syncthreads();
    if (t < 128) red[t] = fmaxf(red[t], red[t+128]);
    __syncthreads();
    if (t < 64) d_g[b*Hd + c] = fmaxf(red[t], red[t+64]);
}

// ---------------- output MLP ----------------
__global__ void k_mlp(const float* __restrict__ o0w, const float* __restrict__ o0b,
                      const float* __restrict__ o1w, const float* __restrict__ o1b,
                      const float* __restrict__ o2w, const float* __restrict__ o2b,
                      float* __restrict__ out){
    int t = threadIdx.x;
    int b = t >> 6, c = t & 63;
    __shared__ float g1s[Bg*Hd], g2s[Bg*Hd];
    float acc = __ldg(&o0b[c]);
    for (int d = 0; d < Hd; d++) acc += d_g[b*Hd+d] * __ldg(&o0w[c*Hd+d]);
    g1s[t] = fmaxf(acc, 0.f);
    __syncthreads();
    acc = __ldg(&o1b[c]);
    for (int d = 0; d < Hd; d++) acc += g1s[b*Hd+d] * __ldg(&o1w[c*Hd+d]);
    g2s[t] = fmaxf(acc, 0.f);
    __syncthreads();
    if (t < Bg){
        float a = __ldg(&o2b[0]);
        for (int d = 0; d < Hd; d++) a += g2s[t*Hd+d] * __ldg(&o2w[d]);
        out[t] = a;
    }
}

// ---------------- launch ----------------
extern "C" void kernel_launch(void* const* d_in, const int* in_sizes, int n_in,
                              void* d_out, int out_size){
    const float* x     = (const float*)d_in[0];
    const int*   batch = (const int*)  d_in[1];
    const float* dn    = (const float*)d_in[2];
    const float* inw   = (const float*)d_in[3];
    const float* inb   = (const float*)d_in[4];
    const float* A[2][8];
    for (int l = 0; l < 2; l++)
        for (int q = 0; q < 8; q++)
            A[l][q] = (const float*)d_in[5 + l*8 + q];
    const float* o0w = (const float*)d_in[21];
    const float* o0b = (const float*)d_in[22];
    const float* o1w = (const float*)d_in[23];
    const float* o1b = (const float*)d_in[24];
    const float* o2w = (const float*)d_in[25];
    const float* o2b = (const float*)d_in[26];
    float* out = (float*)d_out;

    k_bounds<<<1, 32>>>(batch);                 // 0
    k_input<<<Nn/4, 256>>>(x, dn, inw, inb);    // 1

    dim3 tgrid(NS/32, Hd/32), tthr(32, 8);
    for (int l = 0; l < 2; l++){
        k_transpose<<<tgrid, tthr>>>(l);        // 2
        k_dist<<<MAXT, 256>>>(l);               // 3 <- profiled slot
        k_sel<<<NS/8, 256>>>(l);
        k_uv<<<(Nn + UVN - 1)/UVN, H2>>>(l, A[l][0], A[l][1], A[l][2], A[l][3]);
        k_edge<<<(Nn + EN - 1)/EN, 256>>>(l, A[l][4], A[l][5], A[l][6], A[l][7]);
        k_partner<<<Nn/4, 128>>>(l);
        k_pool<<<Nn/4, 256>>>(l);
        if (l == 0) k_compact<<<Bg, 256>>>();
    }

    k_globalpool<<<Bg, 512>>>();
    k_mlp<<<1, Bg*Hd>>>(o0w, o0b, o1w, o1b, o2w, o2b, out);
}